// round 9
// baseline (speedup 1.0000x reference)
#include <cuda_runtime.h>
#include <cuda_bf16.h>
#include <cstdint>

#define BATCH 256
#define SEQ   256
#define EMB   384
#define HD    64
#define NTOT  192   // fused output cols: [q|k|v]

// -------- device scratch (allocation rules: __device__ globals) --------
__device__ float g_q[BATCH * SEQ * HD];
__device__ float g_k[BATCH * SEQ * HD];
__device__ float g_v[BATCH * SEQ * HD];
__device__ __nv_bfloat16 g_Wh[NTOT * EMB];   // weights [n][k], bf16 hi
__device__ __nv_bfloat16 g_Wl[NTOT * EMB];   // residual lo

// ------------------------------- helpers -------------------------------
__device__ __forceinline__ uint32_t smem_u32(const void* p) {
    uint32_t a;
    asm("{ .reg .u64 t; cvta.to.shared.u64 t, %1; cvt.u32.u64 %0, t; }"
        : "=r"(a) : "l"(p));
    return a;
}
__device__ __forceinline__ uint32_t pack_bf2(float a, float b) {
    __nv_bfloat162 t = __floats2bfloat162_rn(a, b);
    return *reinterpret_cast<uint32_t*>(&t);
}
__device__ __forceinline__ void ldsm4(uint32_t* r, uint32_t addr) {
    asm volatile("ldmatrix.sync.aligned.m8n8.x4.shared.b16 {%0,%1,%2,%3}, [%4];"
                 : "=r"(r[0]), "=r"(r[1]), "=r"(r[2]), "=r"(r[3]) : "r"(addr));
}
__device__ __forceinline__ void mma_bf16(float* d, const uint32_t* a,
                                         const uint32_t* b) {
    asm volatile("mma.sync.aligned.m16n8k16.row.col.f32.bf16.bf16.f32 "
                 "{%0,%1,%2,%3}, {%4,%5,%6,%7}, {%8,%9}, {%0,%1,%2,%3};"
                 : "+f"(d[0]), "+f"(d[1]), "+f"(d[2]), "+f"(d[3])
                 : "r"(a[0]), "r"(a[1]), "r"(a[2]), "r"(a[3]),
                   "r"(b[0]), "r"(b[1]));
}

// ---------------------------------------------------------------------------
// Kernel 0: transpose + bf16-split the weights into [n][k] globals.
// ---------------------------------------------------------------------------
__global__ void __launch_bounds__(256) split_w_kernel(
    const float* __restrict__ Wk,
    const float* __restrict__ Wq,
    const float* __restrict__ Wv)
{
    int idx = blockIdx.x * 256 + threadIdx.x;
    if (idx >= NTOT * EMB) return;
    int n = idx / EMB, k = idx % EMB;
    const float* W = (n < 64) ? Wq : ((n < 128) ? Wk : Wv);
    float w = W[(size_t)k * HD + (n & 63)];
    __nv_bfloat16 hi = __float2bfloat16_rn(w);
    g_Wh[idx] = hi;
    g_Wl[idx] = __float2bfloat16_rn(w - __bfloat162float(hi));
}

// ---------------------------------------------------------------------------
// Kernel 1: fused QKV projection via mma.sync bf16, 3-term split:
//   C = Ah*Bh + Ah*Bl + Al*Bh.
//   CTA tile 128(M) x 96(N), BK=32 (two k16 steps per chunk — R6 fix).
//   8 warps: warp_m=wid&3 (32 rows), warp_n=wid>>2 (48 cols).
//   smem rows padded to 112B -> ldmatrix row banks conflict-free.
// ---------------------------------------------------------------------------
#define SMSB   112
#define OFF_AH 0
#define OFF_AL 14336
#define OFF_BH 28672
#define OFF_BL 39424
#define GEMM_SMEM 50176

__global__ void __launch_bounds__(256, 2) qkv_mma_kernel(const float* __restrict__ x)
{
    extern __shared__ char smc[];
    const uint32_t sb = smem_u32(smc);

    const int tid    = threadIdx.x;
    const int lane   = tid & 31;
    const int wid    = tid >> 5;
    const int warp_m = wid & 3;
    const int warp_n = wid >> 2;
    const int row0   = blockIdx.x * 128;
    const int col0   = blockIdx.y * 96;

    float acc[12][4];
    #pragma unroll
    for (int i = 0; i < 12; i++)
        #pragma unroll
        for (int j = 0; j < 4; j++) acc[i][j] = 0.f;

    const uint32_t* Wh32 = (const uint32_t*)g_Wh;
    const uint32_t* Wl32 = (const uint32_t*)g_Wl;

    // base smem addresses for this warp's fragments
    const uint32_t aBase = sb + OFF_AH
                         + (uint32_t)(warp_m * 32 + (lane & 15)) * SMSB
                         + (uint32_t)(lane >> 4) * 16;
    const uint32_t bBase = sb + OFF_BH
                         + (uint32_t)(warp_n * 48 + (lane & 7) + (lane >> 4) * 8) * SMSB
                         + (uint32_t)((lane >> 3) & 1) * 16;

    for (int k0 = 0; k0 < EMB; k0 += 32) {
        // ---- global prefetch into registers ----
        float4 av[4];
        #pragma unroll
        for (int i = 0; i < 4; i++) {
            int idx = tid + i * 256;
            int m = idx >> 3, kq = idx & 7;
            av[i] = *(const float4*)(x + (size_t)(row0 + m) * EMB + k0 + kq * 4);
        }
        uint32_t bh[6], bl[6];
        #pragma unroll
        for (int i = 0; i < 6; i++) {
            int idx = tid + i * 256;
            int nl = idx >> 4, ku = idx & 15;
            size_t o = ((size_t)(col0 + nl) * EMB + k0) / 2 + ku;
            bh[i] = Wh32[o];
            bl[i] = Wl32[o];
        }

        __syncthreads();   // previous iteration's ldmatrix reads are done

        // ---- STS: A split hi/lo on the fly ----
        #pragma unroll
        for (int i = 0; i < 4; i++) {
            int idx = tid + i * 256;
            int m = idx >> 3, kq = idx & 7;
            float4 a = av[i];
            __nv_bfloat162 h0 = __floats2bfloat162_rn(a.x, a.y);
            __nv_bfloat162 h1 = __floats2bfloat162_rn(a.z, a.w);
            float2 f0 = __bfloat1622float2(h0);
            float2 f1 = __bfloat1622float2(h1);
            uint2 hv, lv;
            hv.x = *reinterpret_cast<uint32_t*>(&h0);
            hv.y = *reinterpret_cast<uint32_t*>(&h1);
            lv.x = pack_bf2(a.x - f0.x, a.y - f0.y);
            lv.y = pack_bf2(a.z - f1.x, a.w - f1.y);
            int byte = m * SMSB + kq * 8;
            *(uint2*)(smc + OFF_AH + byte) = hv;
            *(uint2*)(smc + OFF_AL + byte) = lv;
        }
        #pragma unroll
        for (int i = 0; i < 6; i++) {
            int idx = tid + i * 256;
            int nl = idx >> 4, ku = idx & 15;
            int byte = nl * SMSB + ku * 4;
            *(uint32_t*)(smc + OFF_BH + byte) = bh[i];
            *(uint32_t*)(smc + OFF_BL + byte) = bl[i];
        }
        __syncthreads();

        // ---- two k16 steps per BK=32 chunk (the R6 fix) ----
        #pragma unroll
        for (int ks = 0; ks < 2; ks++) {
            const uint32_t ko = (uint32_t)(ks * 32);   // 16 bf16 = 32 bytes

            uint32_t afh[2][4], afl[2][4], bfh[3][4], bfl[3][4];
            #pragma unroll
            for (int mt = 0; mt < 2; mt++) {
                uint32_t ad = aBase + (uint32_t)(mt * 16) * SMSB + ko;
                ldsm4(afh[mt], ad);
                ldsm4(afl[mt], ad + (OFF_AL - OFF_AH));
            }
            #pragma unroll
            for (int bp = 0; bp < 3; bp++) {
                uint32_t bd = bBase + (uint32_t)(bp * 16) * SMSB + ko;
                ldsm4(bfh[bp], bd);
                ldsm4(bfl[bp], bd + (OFF_BL - OFF_BH));
            }

            #pragma unroll
            for (int mt = 0; mt < 2; mt++)
                #pragma unroll
                for (int j = 0; j < 6; j++) {
                    const uint32_t* b2h = &bfh[j >> 1][(j & 1) * 2];
                    const uint32_t* b2l = &bfl[j >> 1][(j & 1) * 2];
                    mma_bf16(acc[mt * 6 + j], afh[mt], b2h);
                    mma_bf16(acc[mt * 6 + j], afh[mt], b2l);
                    mma_bf16(acc[mt * 6 + j], afl[mt], b2h);
                }
        }
    }

    // ---- epilogue: scatter to g_q / g_k / g_v ----
    #pragma unroll
    for (int mt = 0; mt < 2; mt++)
        #pragma unroll
        for (int j = 0; j < 6; j++) {
            int row = row0 + warp_m * 32 + mt * 16 + (lane >> 2);
            int col = col0 + warp_n * 48 + j * 8 + (lane & 3) * 2;
            float* dst = (col < 64) ? g_q : ((col < 128) ? g_k : g_v);
            int cw = col & 63;
            float2 v0 = make_float2(acc[mt * 6 + j][0], acc[mt * 6 + j][1]);
            float2 v1 = make_float2(acc[mt * 6 + j][2], acc[mt * 6 + j][3]);
            *(float2*)(dst + (size_t)row * HD + cw)       = v0;
            *(float2*)(dst + (size_t)(row + 8) * HD + cw) = v1;
        }
}

// ---------------------------------------------------------------------------
// Kernel 2: causal attention, one CTA per batch. 512 threads = 16 warps,
//   2 lanes per row (32 head-dims each, shfl-pair dot reduce).
//   Blocks assigned so each SMSP (wid%4) gets {s, 7-s, 8+s, 15-s}:
//   per-SMSP work exactly equal.
// ---------------------------------------------------------------------------
__global__ void __launch_bounds__(512) attn_kernel(float* __restrict__ out)
{
    extern __shared__ float sm[];
    float* Ks = sm;
    float* Vs = sm + SEQ * HD;

    const int b   = blockIdx.x;
    const int tid = threadIdx.x;
    const size_t base = (size_t)b * SEQ * HD;

    const float4* k4 = (const float4*)(g_k + base);
    const float4* v4 = (const float4*)(g_v + base);
    for (int i = tid; i < SEQ * HD / 4; i += 512) {
        ((float4*)Ks)[i] = k4[i];
        ((float4*)Vs)[i] = v4[i];
    }
    __syncthreads();

    const int wid  = tid >> 5;
    const int lane = tid & 31;
    const int s    = wid & 3;          // SMSP id
    const int i4   = wid >> 2;
    const int blk  = (i4 == 0) ? s : (i4 == 1) ? 7 - s
                   : (i4 == 2) ? 8 + s : 15 - s;

    const int row = blk * 16 + (lane >> 1);
    const int d0  = (lane & 1) * 32;

    float q[32];
    {
        const float4* qp = (const float4*)(g_q + base + (size_t)row * HD + d0);
        #pragma unroll
        for (int i = 0; i < 8; i++) *(float4*)&q[i * 4] = qp[i];
    }
    float acc[32];
    #pragma unroll
    for (int d = 0; d < 32; d++) acc[d] = 0.f;

    float m = -1e30f, l = 0.f;

    for (int j = 0; j <= row; j++) {
        const float4* kr = (const float4*)(Ks + j * HD + d0);
        float s0 = 0.f, s1 = 0.f, s2 = 0.f, s3 = 0.f;
        #pragma unroll
        for (int i = 0; i < 8; i++) {
            float4 kv = kr[i];
            s0 = fmaf(q[i * 4 + 0], kv.x, s0);
            s1 = fmaf(q[i * 4 + 1], kv.y, s1);
            s2 = fmaf(q[i * 4 + 2], kv.z, s2);
            s3 = fmaf(q[i * 4 + 3], kv.w, s3);
        }
        float sp = (s0 + s1) + (s2 + s3);
        sp += __shfl_xor_sync(__activemask(), sp, 1);   // pair lanes share row
        float sc = sp * 0.125f;                         // 1/sqrt(64)

        if (sc > m) {                                   // ~ln(T) hits per row
            float r = __expf(m - sc);
            l *= r;
            #pragma unroll
            for (int d = 0; d < 32; d++) acc[d] *= r;
            m = sc;
        }
        float p = __expf(sc - m);
        l += p;

        const float4* vr = (const float4*)(Vs + j * HD + d0);
        #pragma unroll
        for (int i = 0; i < 8; i++) {
            float4 vv = vr[i];
            acc[i * 4 + 0] = fmaf(p, vv.x, acc[i * 4 + 0]);
            acc[i * 4 + 1] = fmaf(p, vv.y, acc[i * 4 + 1]);
            acc[i * 4 + 2] = fmaf(p, vv.z, acc[i * 4 + 2]);
            acc[i * 4 + 3] = fmaf(p, vv.w, acc[i * 4 + 3]);
        }
    }

    const float il = 1.f / l;
    float4* op = (float4*)(out + base + (size_t)row * HD + d0);
    #pragma unroll
    for (int i = 0; i < 8; i++) {
        float4 o;
        o.x = acc[i * 4 + 0] * il;
        o.y = acc[i * 4 + 1] * il;
        o.z = acc[i * 4 + 2] * il;
        o.w = acc[i * 4 + 3] * il;
        op[i] = o;
    }
}

// ---------------------------------------------------------------------------
// Launch. Inputs: x, Wk, Wq, Wv. Output [B, T, H] f32.
// ---------------------------------------------------------------------------
extern "C" void kernel_launch(void* const* d_in, const int* in_sizes, int n_in,
                              void* d_out, int out_size)
{
    const float* x  = (const float*)d_in[0];
    const float* Wk = (const float*)d_in[1];
    const float* Wq = (const float*)d_in[2];
    const float* Wv = (const float*)d_in[3];
    float* out = (float*)d_out;

    split_w_kernel<<<(NTOT * EMB + 255) / 256, 256>>>(Wk, Wq, Wv);

    cudaFuncSetAttribute(qkv_mma_kernel,
                         cudaFuncAttributeMaxDynamicSharedMemorySize, GEMM_SMEM);
    qkv_mma_kernel<<<dim3(512, 2), 256, GEMM_SMEM>>>(x);

    const int attn_smem = 2 * SEQ * HD * (int)sizeof(float);   // 128 KB
    cudaFuncSetAttribute(attn_kernel,
                         cudaFuncAttributeMaxDynamicSharedMemorySize, attn_smem);
    attn_kernel<<<BATCH, 512, attn_smem>>>(out);
}